// round 6
// baseline (speedup 1.0000x reference)
#include <cuda_runtime.h>
#include <cstdint>

#define DIN  32
#define DOUT 32
#define TPB  256
#define NWARP (TPB / 32)
#define TILE_ROWS 128                      // rows per warp-iteration
#define STRIDE_F  36                       // padded smem row stride (floats); 36*4=144B, 16B-aligned, conflict-free
#define TILE_FLOATS (TILE_ROWS * STRIDE_F) // 4608 floats = 18 KB per warp
#define SMEM_BYTES (NWARP * TILE_FLOATS * 4)  // 147456 B

// Packed 2-wide fp32 FMA (Blackwell f32x2 pipe; PTX-only).
__device__ __forceinline__ unsigned long long fma2(unsigned long long a,
                                                   unsigned long long b,
                                                   unsigned long long c) {
    unsigned long long d;
    asm("fma.rn.f32x2 %0, %1, %2, %3;" : "=l"(d) : "l"(a), "l"(b), "l"(c));
    return d;
}

union U64F2 { unsigned long long u; float2 f; };

extern "C" __global__ void __launch_bounds__(TPB, 1)
layer_relu_kernel(const float* __restrict__ x,
                  const float* __restrict__ W,
                  float* __restrict__ out,
                  int nrows)
{
    extern __shared__ float smem[];
    const int lane = threadIdx.x & 31;
    const int wid  = threadIdx.x >> 5;
    float* tile = smem + wid * TILE_FLOATS;   // warp-private tile

    const int gwarp  = blockIdx.x * NWARP + wid;
    const int nwarps = gridDim.x * NWARP;

    const int ntiles = nrows / TILE_ROWS;     // full tiles

    for (int t = gwarp; t < ntiles; t += nwarps) {
        const long long rowBase = (long long)t * TILE_ROWS;

        // ---- Step 1: coalesced gmem -> smem tile (16 KB as 32x LDG.128/STS.128)
        {
            const float4* gx = reinterpret_cast<const float4*>(x + rowBase * DIN);
            #pragma unroll
            for (int i = 0; i < 32; ++i) {
                const int idx = i * 32 + lane;        // 16B chunk 0..1023
                float4 v = __ldg(&gx[idx]);
                const int r = idx >> 3, c = idx & 7;
                *reinterpret_cast<float4*>(&tile[r * STRIDE_F + c * 4]) = v;
            }
        }
        __syncwarp();

        // ---- Step 2: per-thread rows (lane, lane+32, lane+64, lane+96) -> regs
        unsigned long long X[4][16];
        #pragma unroll
        for (int rr = 0; rr < 4; ++rr) {
            const int r = lane + 32 * rr;
            #pragma unroll
            for (int j = 0; j < 8; ++j) {
                ulonglong2 v = *reinterpret_cast<const ulonglong2*>(
                    &tile[r * STRIDE_F + j * 4]);
                X[rr][2 * j]     = v.x;
                X[rr][2 * j + 1] = v.y;
            }
        }
        __syncwarp();   // tile x-data now dead; safe to overwrite with results

        // ---- Step 3: compute; W streamed via uniform __ldg (L1-resident, line-dedup)
        #pragma unroll
        for (int og = 0; og < 8; ++og) {
            float res[4][4];
            #pragma unroll
            for (int c = 0; c < 4; ++c) {
                const int o = og * 4 + c;
                const ulonglong2* wr =
                    reinterpret_cast<const ulonglong2*>(W + o * DIN);
                ulonglong2 w[8];
                #pragma unroll
                for (int j = 0; j < 8; ++j) w[j] = __ldg(&wr[j]);
                #pragma unroll
                for (int rr = 0; rr < 4; ++rr) {
                    unsigned long long acc = 0ull;
                    #pragma unroll
                    for (int j = 0; j < 8; ++j) {
                        acc = fma2(X[rr][2 * j],     w[j].x, acc);
                        acc = fma2(X[rr][2 * j + 1], w[j].y, acc);
                    }
                    U64F2 u; u.u = acc;
                    res[rr][c] = fmaxf(u.f.x + u.f.y, 0.0f);
                }
            }
            #pragma unroll
            for (int rr = 0; rr < 4; ++rr) {
                const int r = lane + 32 * rr;
                *reinterpret_cast<float4*>(&tile[r * STRIDE_F + og * 4]) =
                    make_float4(res[rr][0], res[rr][1], res[rr][2], res[rr][3]);
            }
        }
        __syncwarp();

        // ---- Step 4: coalesced smem tile -> gmem out
        {
            float4* gout = reinterpret_cast<float4*>(out + rowBase * DOUT);
            #pragma unroll
            for (int i = 0; i < 32; ++i) {
                const int idx = i * 32 + lane;
                const int r = idx >> 3, c = idx & 7;
                gout[idx] = *reinterpret_cast<const float4*>(
                    &tile[r * STRIDE_F + c * 4]);
            }
        }
        __syncwarp();   // before next iteration's STS overwrites the tile
    }

    // ---- Tail: leftover rows (< TILE_ROWS) — simple per-lane path
    const long long tailBase = (long long)ntiles * TILE_ROWS;
    if (tailBase < nrows && gwarp == 0) {
        for (long long r = tailBase + lane; r < nrows; r += 32) {
            float xv[DIN];
            #pragma unroll
            for (int k = 0; k < DIN; ++k) xv[k] = x[r * DIN + k];
            #pragma unroll
            for (int o = 0; o < DOUT; ++o) {
                float s = 0.f;
                #pragma unroll
                for (int k = 0; k < DIN; ++k) s = fmaf(xv[k], __ldg(&W[o * DIN + k]), s);
                out[r * DOUT + o] = fmaxf(s, 0.f);
            }
        }
    }
}

extern "C" void kernel_launch(void* const* d_in, const int* in_sizes, int n_in,
                              void* d_out, int out_size) {
    const float* x = (const float*)d_in[0];   // [N, 32] fp32
    const float* W = (const float*)d_in[1];   // [32, 32] fp32
    float* out     = (float*)d_out;           // [N, 32] fp32

    const int nrows = in_sizes[0] / DIN;      // 8388608

    static int smem_set = 0;
    // cudaFuncSetAttribute is idempotent & host-side; safe under graph capture.
    cudaFuncSetAttribute(layer_relu_kernel,
                         cudaFuncAttributeMaxDynamicSharedMemorySize, SMEM_BYTES);
    (void)smem_set;

    const int blocks = 2048;                  // 1 resident block/SM (144 KB smem)
    layer_relu_kernel<<<blocks, TPB, SMEM_BYTES>>>(x, W, out, nrows);
}

// round 7
// speedup vs baseline: 1.0019x; 1.0019x over previous
#include <cuda_runtime.h>
#include <cstdint>

#define DIN  32
#define DOUT 32
#define TPB  256
#define NWARP (TPB / 32)
#define TILE_ROWS 128                      // rows per warp-iteration
#define STRIDE_F  36                       // padded smem row stride (floats); 36*4=144B, 16B-aligned, conflict-free
#define TILE_FLOATS (TILE_ROWS * STRIDE_F) // 4608 floats = 18 KB per warp
#define SMEM_BYTES (NWARP * TILE_FLOATS * 4)  // 147456 B

// Packed 2-wide fp32 FMA (Blackwell f32x2 pipe; PTX-only).
__device__ __forceinline__ unsigned long long fma2(unsigned long long a,
                                                   unsigned long long b,
                                                   unsigned long long c) {
    unsigned long long d;
    asm("fma.rn.f32x2 %0, %1, %2, %3;" : "=l"(d) : "l"(a), "l"(b), "l"(c));
    return d;
}

union U64F2 { unsigned long long u; float2 f; };

extern "C" __global__ void __launch_bounds__(TPB, 1)
layer_relu_kernel(const float* __restrict__ x,
                  const float* __restrict__ W,
                  float* __restrict__ out,
                  int nrows)
{
    extern __shared__ float smem[];
    const int lane = threadIdx.x & 31;
    const int wid  = threadIdx.x >> 5;
    float* tile = smem + wid * TILE_FLOATS;   // warp-private tile

    const int gwarp  = blockIdx.x * NWARP + wid;
    const int nwarps = gridDim.x * NWARP;

    const int ntiles = nrows / TILE_ROWS;     // full tiles

    for (int t = gwarp; t < ntiles; t += nwarps) {
        const long long rowBase = (long long)t * TILE_ROWS;

        // ---- Step 1: coalesced gmem -> smem tile (16 KB as 32x LDG.128/STS.128)
        {
            const float4* gx = reinterpret_cast<const float4*>(x + rowBase * DIN);
            #pragma unroll
            for (int i = 0; i < 32; ++i) {
                const int idx = i * 32 + lane;        // 16B chunk 0..1023
                float4 v = __ldg(&gx[idx]);
                const int r = idx >> 3, c = idx & 7;
                *reinterpret_cast<float4*>(&tile[r * STRIDE_F + c * 4]) = v;
            }
        }
        __syncwarp();

        // ---- Step 2: per-thread rows (lane, lane+32, lane+64, lane+96) -> regs
        unsigned long long X[4][16];
        #pragma unroll
        for (int rr = 0; rr < 4; ++rr) {
            const int r = lane + 32 * rr;
            #pragma unroll
            for (int j = 0; j < 8; ++j) {
                ulonglong2 v = *reinterpret_cast<const ulonglong2*>(
                    &tile[r * STRIDE_F + j * 4]);
                X[rr][2 * j]     = v.x;
                X[rr][2 * j + 1] = v.y;
            }
        }
        __syncwarp();   // tile x-data now dead; safe to overwrite with results

        // ---- Step 3: compute; W streamed via uniform __ldg (L1-resident, line-dedup)
        #pragma unroll
        for (int og = 0; og < 8; ++og) {
            float res[4][4];
            #pragma unroll
            for (int c = 0; c < 4; ++c) {
                const int o = og * 4 + c;
                const ulonglong2* wr =
                    reinterpret_cast<const ulonglong2*>(W + o * DIN);
                ulonglong2 w[8];
                #pragma unroll
                for (int j = 0; j < 8; ++j) w[j] = __ldg(&wr[j]);
                #pragma unroll
                for (int rr = 0; rr < 4; ++rr) {
                    unsigned long long acc = 0ull;
                    #pragma unroll
                    for (int j = 0; j < 8; ++j) {
                        acc = fma2(X[rr][2 * j],     w[j].x, acc);
                        acc = fma2(X[rr][2 * j + 1], w[j].y, acc);
                    }
                    U64F2 u; u.u = acc;
                    res[rr][c] = fmaxf(u.f.x + u.f.y, 0.0f);
                }
            }
            #pragma unroll
            for (int rr = 0; rr < 4; ++rr) {
                const int r = lane + 32 * rr;
                *reinterpret_cast<float4*>(&tile[r * STRIDE_F + og * 4]) =
                    make_float4(res[rr][0], res[rr][1], res[rr][2], res[rr][3]);
            }
        }
        __syncwarp();

        // ---- Step 4: coalesced smem tile -> gmem out
        {
            float4* gout = reinterpret_cast<float4*>(out + rowBase * DOUT);
            #pragma unroll
            for (int i = 0; i < 32; ++i) {
                const int idx = i * 32 + lane;
                const int r = idx >> 3, c = idx & 7;
                gout[idx] = *reinterpret_cast<const float4*>(
                    &tile[r * STRIDE_F + c * 4]);
            }
        }
        __syncwarp();   // before next iteration's STS overwrites the tile
    }

    // ---- Tail: leftover rows (< TILE_ROWS) — simple per-lane path
    const long long tailBase = (long long)ntiles * TILE_ROWS;
    if (tailBase < nrows && gwarp == 0) {
        for (long long r = tailBase + lane; r < nrows; r += 32) {
            float xv[DIN];
            #pragma unroll
            for (int k = 0; k < DIN; ++k) xv[k] = x[r * DIN + k];
            #pragma unroll
            for (int o = 0; o < DOUT; ++o) {
                float s = 0.f;
                #pragma unroll
                for (int k = 0; k < DIN; ++k) s = fmaf(xv[k], __ldg(&W[o * DIN + k]), s);
                out[r * DOUT + o] = fmaxf(s, 0.f);
            }
        }
    }
}

extern "C" void kernel_launch(void* const* d_in, const int* in_sizes, int n_in,
                              void* d_out, int out_size) {
    const float* x = (const float*)d_in[0];   // [N, 32] fp32
    const float* W = (const float*)d_in[1];   // [32, 32] fp32
    float* out     = (float*)d_out;           // [N, 32] fp32

    const int nrows = in_sizes[0] / DIN;      // 8388608

    static int smem_set = 0;
    // cudaFuncSetAttribute is idempotent & host-side; safe under graph capture.
    cudaFuncSetAttribute(layer_relu_kernel,
                         cudaFuncAttributeMaxDynamicSharedMemorySize, SMEM_BYTES);
    (void)smem_set;

    const int blocks = 2048;                  // 1 resident block/SM (144 KB smem)
    layer_relu_kernel<<<blocks, TPB, SMEM_BYTES>>>(x, W, out, nrows);
}

// round 8
// speedup vs baseline: 1.0149x; 1.0130x over previous
#include <cuda_runtime.h>
#include <cstdint>

#define DIN  32
#define DOUT 32
#define TPB  256
#define NWARP (TPB / 32)
#define TILE_ROWS 128                      // rows per warp-iteration
#define STRIDE_F  36                       // padded smem row stride (floats); 36*4=144B, 16B-aligned, conflict-free
#define TILE_FLOATS (TILE_ROWS * STRIDE_F) // 4608 floats = 18 KB per warp
#define SMEM_BYTES (NWARP * TILE_FLOATS * 4)  // 147456 B

// Packed 2-wide fp32 FMA (Blackwell f32x2 pipe; PTX-only).
__device__ __forceinline__ unsigned long long fma2(unsigned long long a,
                                                   unsigned long long b,
                                                   unsigned long long c) {
    unsigned long long d;
    asm("fma.rn.f32x2 %0, %1, %2, %3;" : "=l"(d) : "l"(a), "l"(b), "l"(c));
    return d;
}

union U64F2 { unsigned long long u; float2 f; };

extern "C" __global__ void __launch_bounds__(TPB, 1)
layer_relu_kernel(const float* __restrict__ x,
                  const float* __restrict__ W,
                  float* __restrict__ out,
                  int nrows)
{
    extern __shared__ float smem[];
    const int lane = threadIdx.x & 31;
    const int wid  = threadIdx.x >> 5;
    float* tile = smem + wid * TILE_FLOATS;   // warp-private tile

    const int gwarp  = blockIdx.x * NWARP + wid;
    const int nwarps = gridDim.x * NWARP;

    const int ntiles = nrows / TILE_ROWS;     // full tiles

    for (int t = gwarp; t < ntiles; t += nwarps) {
        const long long rowBase = (long long)t * TILE_ROWS;

        // ---- Step 1: coalesced gmem -> smem tile (16 KB as 32x LDG.128/STS.128)
        {
            const float4* gx = reinterpret_cast<const float4*>(x + rowBase * DIN);
            #pragma unroll
            for (int i = 0; i < 32; ++i) {
                const int idx = i * 32 + lane;        // 16B chunk 0..1023
                float4 v = __ldg(&gx[idx]);
                const int r = idx >> 3, c = idx & 7;
                *reinterpret_cast<float4*>(&tile[r * STRIDE_F + c * 4]) = v;
            }
        }
        __syncwarp();

        // ---- Step 2: per-thread rows (lane, lane+32, lane+64, lane+96) -> regs
        unsigned long long X[4][16];
        #pragma unroll
        for (int rr = 0; rr < 4; ++rr) {
            const int r = lane + 32 * rr;
            #pragma unroll
            for (int j = 0; j < 8; ++j) {
                ulonglong2 v = *reinterpret_cast<const ulonglong2*>(
                    &tile[r * STRIDE_F + j * 4]);
                X[rr][2 * j]     = v.x;
                X[rr][2 * j + 1] = v.y;
            }
        }
        __syncwarp();   // tile x-data now dead; safe to overwrite with results

        // ---- Step 3: compute; W streamed via uniform __ldg (L1-resident, line-dedup)
        #pragma unroll
        for (int og = 0; og < 8; ++og) {
            float res[4][4];
            #pragma unroll
            for (int c = 0; c < 4; ++c) {
                const int o = og * 4 + c;
                const ulonglong2* wr =
                    reinterpret_cast<const ulonglong2*>(W + o * DIN);
                ulonglong2 w[8];
                #pragma unroll
                for (int j = 0; j < 8; ++j) w[j] = __ldg(&wr[j]);
                #pragma unroll
                for (int rr = 0; rr < 4; ++rr) {
                    unsigned long long acc = 0ull;
                    #pragma unroll
                    for (int j = 0; j < 8; ++j) {
                        acc = fma2(X[rr][2 * j],     w[j].x, acc);
                        acc = fma2(X[rr][2 * j + 1], w[j].y, acc);
                    }
                    U64F2 u; u.u = acc;
                    res[rr][c] = fmaxf(u.f.x + u.f.y, 0.0f);
                }
            }
            #pragma unroll
            for (int rr = 0; rr < 4; ++rr) {
                const int r = lane + 32 * rr;
                *reinterpret_cast<float4*>(&tile[r * STRIDE_F + og * 4]) =
                    make_float4(res[rr][0], res[rr][1], res[rr][2], res[rr][3]);
            }
        }
        __syncwarp();

        // ---- Step 4: coalesced smem tile -> gmem out
        {
            float4* gout = reinterpret_cast<float4*>(out + rowBase * DOUT);
            #pragma unroll
            for (int i = 0; i < 32; ++i) {
                const int idx = i * 32 + lane;
                const int r = idx >> 3, c = idx & 7;
                gout[idx] = *reinterpret_cast<const float4*>(
                    &tile[r * STRIDE_F + c * 4]);
            }
        }
        __syncwarp();   // before next iteration's STS overwrites the tile
    }

    // ---- Tail: leftover rows (< TILE_ROWS) — simple per-lane path
    const long long tailBase = (long long)ntiles * TILE_ROWS;
    if (tailBase < nrows && gwarp == 0) {
        for (long long r = tailBase + lane; r < nrows; r += 32) {
            float xv[DIN];
            #pragma unroll
            for (int k = 0; k < DIN; ++k) xv[k] = x[r * DIN + k];
            #pragma unroll
            for (int o = 0; o < DOUT; ++o) {
                float s = 0.f;
                #pragma unroll
                for (int k = 0; k < DIN; ++k) s = fmaf(xv[k], __ldg(&W[o * DIN + k]), s);
                out[r * DOUT + o] = fmaxf(s, 0.f);
            }
        }
    }
}

extern "C" void kernel_launch(void* const* d_in, const int* in_sizes, int n_in,
                              void* d_out, int out_size) {
    const float* x = (const float*)d_in[0];   // [N, 32] fp32
    const float* W = (const float*)d_in[1];   // [32, 32] fp32
    float* out     = (float*)d_out;           // [N, 32] fp32

    const int nrows = in_sizes[0] / DIN;      // 8388608

    static int smem_set = 0;
    // cudaFuncSetAttribute is idempotent & host-side; safe under graph capture.
    cudaFuncSetAttribute(layer_relu_kernel,
                         cudaFuncAttributeMaxDynamicSharedMemorySize, SMEM_BYTES);
    (void)smem_set;

    const int blocks = 2048;                  // 1 resident block/SM (144 KB smem)
    layer_relu_kernel<<<blocks, TPB, SMEM_BYTES>>>(x, W, out, nrows);
}

// round 9
// speedup vs baseline: 1.0374x; 1.0222x over previous
#include <cuda_runtime.h>
#include <cstdint>

#define DIN  32
#define DOUT 32
#define TPB  256
#define NWARP (TPB / 32)
#define RPT  2                              // rows per thread (reg pressure: X = 64 regs)
#define TILE_ROWS (32 * RPT)                // 64 rows per warp-tile
#define STRIDE_F  36                        // padded smem row stride (floats): 16B-aligned, conflict-free
#define TILE_FLOATS (TILE_ROWS * STRIDE_F)  // 2304 floats = 9216 B per warp
#define SMEM_BYTES (NWARP * TILE_FLOATS * 4)  // 73728 B per block -> 2 blocks/SM

// Packed 2-wide fp32 FMA (Blackwell f32x2 pipe; PTX-only).
__device__ __forceinline__ unsigned long long fma2(unsigned long long a,
                                                   unsigned long long b,
                                                   unsigned long long c) {
    unsigned long long d;
    asm("fma.rn.f32x2 %0, %1, %2, %3;" : "=l"(d) : "l"(a), "l"(b), "l"(c));
    return d;
}

union U64F2 { unsigned long long u; float2 f; };

extern "C" __global__ void __launch_bounds__(TPB, 2)
layer_relu_kernel(const float* __restrict__ x,
                  const float* __restrict__ W,
                  float* __restrict__ out,
                  int nrows)
{
    extern __shared__ float smem[];
    const int lane = threadIdx.x & 31;
    const int wid  = threadIdx.x >> 5;
    float* tile = smem + wid * TILE_FLOATS;   // warp-private tile

    const int gwarp  = blockIdx.x * NWARP + wid;
    const int nwarps = gridDim.x * NWARP;
    const int ntiles = nrows / TILE_ROWS;

    for (int t = gwarp; t < ntiles; t += nwarps) {
        const long long rowBase = (long long)t * TILE_ROWS;

        // ---- Step 1: coalesced gmem -> smem (64 rows x 128B = 16x LDG.128/lane-iter)
        {
            const float4* gx = reinterpret_cast<const float4*>(x + rowBase * DIN);
            #pragma unroll
            for (int i = 0; i < 16; ++i) {
                const int idx = i * 32 + lane;            // float4 chunk 0..511
                float4 v = __ldg(&gx[idx]);
                const int r = idx >> 3, c = idx & 7;
                *reinterpret_cast<float4*>(&tile[r * STRIDE_F + c * 4]) = v;
            }
        }
        __syncwarp();

        // ---- Step 2: per-thread rows (lane, lane+32) -> registers
        unsigned long long X[RPT][16];
        #pragma unroll
        for (int rr = 0; rr < RPT; ++rr) {
            const int r = lane + 32 * rr;
            #pragma unroll
            for (int j = 0; j < 8; ++j) {
                ulonglong2 v = *reinterpret_cast<const ulonglong2*>(
                    &tile[r * STRIDE_F + j * 4]);
                X[rr][2 * j]     = v.x;
                X[rr][2 * j + 1] = v.y;
            }
        }
        __syncwarp();   // x-tile dead; results will overwrite it

        // ---- Step 3: compute. W via uniform __ldg (L1-resident, line-dedup'd)
        #pragma unroll
        for (int og = 0; og < 8; ++og) {
            float res[RPT][4];
            #pragma unroll
            for (int c = 0; c < 4; ++c) {
                const int o = og * 4 + c;
                const ulonglong2* wr =
                    reinterpret_cast<const ulonglong2*>(W + o * DIN);
                ulonglong2 w[8];
                #pragma unroll
                for (int j = 0; j < 8; ++j) w[j] = __ldg(&wr[j]);
                #pragma unroll
                for (int rr = 0; rr < RPT; ++rr) {
                    unsigned long long acc = 0ull;
                    #pragma unroll
                    for (int j = 0; j < 8; ++j) {
                        acc = fma2(X[rr][2 * j],     w[j].x, acc);
                        acc = fma2(X[rr][2 * j + 1], w[j].y, acc);
                    }
                    U64F2 u; u.u = acc;
                    res[rr][c] = fmaxf(u.f.x + u.f.y, 0.0f);
                }
            }
            #pragma unroll
            for (int rr = 0; rr < RPT; ++rr) {
                const int r = lane + 32 * rr;
                *reinterpret_cast<float4*>(&tile[r * STRIDE_F + og * 4]) =
                    make_float4(res[rr][0], res[rr][1], res[rr][2], res[rr][3]);
            }
        }
        __syncwarp();

        // ---- Step 4: coalesced smem -> gmem out
        {
            float4* gout = reinterpret_cast<float4*>(out + rowBase * DOUT);
            #pragma unroll
            for (int i = 0; i < 16; ++i) {
                const int idx = i * 32 + lane;
                const int r = idx >> 3, c = idx & 7;
                gout[idx] = *reinterpret_cast<const float4*>(
                    &tile[r * STRIDE_F + c * 4]);
            }
        }
        __syncwarp();   // before next iteration's stores reuse the tile
    }

    // ---- Tail: leftover rows (< TILE_ROWS)
    const long long tailBase = (long long)ntiles * TILE_ROWS;
    if (tailBase < nrows && gwarp == 0) {
        for (long long r = tailBase + lane; r < nrows; r += 32) {
            float xv[DIN];
            #pragma unroll
            for (int k = 0; k < DIN; ++k) xv[k] = x[r * DIN + k];
            #pragma unroll
            for (int o = 0; o < DOUT; ++o) {
                float s = 0.f;
                #pragma unroll
                for (int k = 0; k < DIN; ++k)
                    s = fmaf(xv[k], __ldg(&W[o * DIN + k]), s);
                out[r * DOUT + o] = fmaxf(s, 0.f);
            }
        }
    }
}

extern "C" void kernel_launch(void* const* d_in, const int* in_sizes, int n_in,
                              void* d_out, int out_size) {
    const float* x = (const float*)d_in[0];   // [N, 32] fp32
    const float* W = (const float*)d_in[1];   // [32, 32] fp32
    float* out     = (float*)d_out;           // [N, 32] fp32

    const int nrows = in_sizes[0] / DIN;      // 8388608

    cudaFuncSetAttribute(layer_relu_kernel,
                         cudaFuncAttributeMaxDynamicSharedMemorySize, SMEM_BYTES);

    const int blocks = 4096;                  // grid-stride over 131072 tiles
    layer_relu_kernel<<<blocks, TPB, SMEM_BYTES>>>(x, W, out, nrows);
}

// round 10
// speedup vs baseline: 2.1749x; 2.0964x over previous
#include <cuda_runtime.h>
#include <cstdint>

#define DIN  32
#define DOUT 32
#define TPB  256
#define NWARP (TPB / 32)
#define RPT  2                              // rows per thread (X = 64 regs)
#define TILE_ROWS (32 * RPT)                // 64 rows per warp-tile
#define STRIDE_F  36                        // padded smem row stride (floats)
#define TILE_FLOATS (TILE_ROWS * STRIDE_F)  // 2304 floats = 9216 B per warp
#define SMEM_BYTES (NWARP * TILE_FLOATS * 4)  // 73728 B per block -> 2 blocks/SM

// W lives in constant memory: the constant port broadcasts uniform reads to all
// lanes for free, entirely off the L1/smem return crossbar (the bottleneck in
// every previous round). Filled per-call via async D2D symbol copy.
__constant__ __align__(16) float Wc[DOUT * DIN];

// Packed 2-wide fp32 FMA (Blackwell f32x2 pipe; PTX-only).
__device__ __forceinline__ unsigned long long fma2(unsigned long long a,
                                                   unsigned long long b,
                                                   unsigned long long c) {
    unsigned long long d;
    asm("fma.rn.f32x2 %0, %1, %2, %3;" : "=l"(d) : "l"(a), "l"(b), "l"(c));
    return d;
}

union U64F2 { unsigned long long u; float2 f; };

extern "C" __global__ void __launch_bounds__(TPB, 2)
layer_relu_kernel(const float* __restrict__ x,
                  float* __restrict__ out,
                  int nrows)
{
    extern __shared__ float smem[];
    const int lane = threadIdx.x & 31;
    const int wid  = threadIdx.x >> 5;
    float* tile = smem + wid * TILE_FLOATS;   // warp-private tile

    const int gwarp  = blockIdx.x * NWARP + wid;
    const int nwarps = gridDim.x * NWARP;
    const int ntiles = nrows / TILE_ROWS;

    for (int t = gwarp; t < ntiles; t += nwarps) {
        const long long rowBase = (long long)t * TILE_ROWS;

        // ---- Step 1: coalesced gmem -> smem (64 rows x 128 B)
        {
            const float4* gx = reinterpret_cast<const float4*>(x + rowBase * DIN);
            #pragma unroll
            for (int i = 0; i < 16; ++i) {
                const int idx = i * 32 + lane;            // float4 chunk 0..511
                float4 v = __ldg(&gx[idx]);
                const int r = idx >> 3, c = idx & 7;
                *reinterpret_cast<float4*>(&tile[r * STRIDE_F + c * 4]) = v;
            }
        }
        __syncwarp();

        // ---- Step 2: per-thread rows (lane, lane+32) -> registers
        unsigned long long X[RPT][16];
        #pragma unroll
        for (int rr = 0; rr < RPT; ++rr) {
            const int r = lane + 32 * rr;
            #pragma unroll
            for (int j = 0; j < 8; ++j) {
                ulonglong2 v = *reinterpret_cast<const ulonglong2*>(
                    &tile[r * STRIDE_F + j * 4]);
                X[rr][2 * j]     = v.x;
                X[rr][2 * j + 1] = v.y;
            }
        }
        __syncwarp();   // x-tile dead; results will overwrite it

        // ---- Step 3: compute. W from __constant__ (dedicated const port,
        //      fully-unrolled -> immediate const-bank addresses -> LDC/LDCU)
        #pragma unroll
        for (int og = 0; og < 8; ++og) {
            float res[RPT][4];
            #pragma unroll
            for (int c = 0; c < 4; ++c) {
                const int o = og * 4 + c;
                const ulonglong2* wr =
                    reinterpret_cast<const ulonglong2*>(&Wc[o * DIN]);
                #pragma unroll
                for (int rr = 0; rr < RPT; ++rr) {
                    unsigned long long acc = 0ull;
                    #pragma unroll
                    for (int j = 0; j < 8; ++j) {
                        const ulonglong2 w = wr[j];
                        acc = fma2(X[rr][2 * j],     w.x, acc);
                        acc = fma2(X[rr][2 * j + 1], w.y, acc);
                    }
                    U64F2 u; u.u = acc;
                    res[rr][c] = fmaxf(u.f.x + u.f.y, 0.0f);
                }
            }
            #pragma unroll
            for (int rr = 0; rr < RPT; ++rr) {
                const int r = lane + 32 * rr;
                *reinterpret_cast<float4*>(&tile[r * STRIDE_F + og * 4]) =
                    make_float4(res[rr][0], res[rr][1], res[rr][2], res[rr][3]);
            }
        }
        __syncwarp();

        // ---- Step 4: coalesced smem -> gmem out
        {
            float4* gout = reinterpret_cast<float4*>(out + rowBase * DOUT);
            #pragma unroll
            for (int i = 0; i < 16; ++i) {
                const int idx = i * 32 + lane;
                const int r = idx >> 3, c = idx & 7;
                gout[idx] = *reinterpret_cast<const float4*>(
                    &tile[r * STRIDE_F + c * 4]);
            }
        }
        __syncwarp();
    }

    // ---- Tail: leftover rows (< TILE_ROWS); never taken for N=8388608
    const long long tailBase = (long long)ntiles * TILE_ROWS;
    if (tailBase < nrows && gwarp == 0) {
        for (long long r = tailBase + lane; r < nrows; r += 32) {
            float xv[DIN];
            #pragma unroll
            for (int k = 0; k < DIN; ++k) xv[k] = x[r * DIN + k];
            #pragma unroll
            for (int o = 0; o < DOUT; ++o) {
                float s = 0.f;
                #pragma unroll
                for (int k = 0; k < DIN; ++k)
                    s = fmaf(xv[k], Wc[o * DIN + k], s);
                out[r * DOUT + o] = fmaxf(s, 0.f);
            }
        }
    }
}

extern "C" void kernel_launch(void* const* d_in, const int* in_sizes, int n_in,
                              void* d_out, int out_size) {
    const float* x = (const float*)d_in[0];   // [N, 32] fp32
    const float* W = (const float*)d_in[1];   // [32, 32] fp32
    float* out     = (float*)d_out;           // [N, 32] fp32

    const int nrows = in_sizes[0] / DIN;      // 8388608

    cudaFuncSetAttribute(layer_relu_kernel,
                         cudaFuncAttributeMaxDynamicSharedMemorySize, SMEM_BYTES);

    // Device-to-device copy into the constant bank; captures as a memcpy node.
    cudaMemcpyToSymbolAsync(Wc, W, DOUT * DIN * sizeof(float), 0,
                            cudaMemcpyDeviceToDevice, 0);

    const int blocks = 4096;                  // grid-stride over 131072 tiles
    layer_relu_kernel<<<blocks, TPB, SMEM_BYTES>>>(x, out, nrows);
}